// round 3
// baseline (speedup 1.0000x reference)
#include <cuda_runtime.h>
#include <cfloat>

// Reverse cummax along axis 1 of [B=16, H=128, W=128, C=256] fp32.
// One thread per (b, w, c4) float4-column. Walk h backward with a running max.
// R2: batch 8 independent LDG.128 per iteration ahead of the dependent FMNMX
// chain (MLP ~8/warp), streaming cache hints (touch-once data).

static constexpr int B = 16;
static constexpr int H = 128;
static constexpr int W = 128;
static constexpr int C = 256;
static constexpr int C4 = C / 4;            // 64 float4 per row
static constexpr int STRIDE_H = W * C4;     // 8192 float4 between h slices
static constexpr int COLS = B * W * C4;     // 131072 columns
static constexpr int PER_B = W * C4;        // 8192 columns per batch
static constexpr long PER_B_ELEMS = (long)H * W * C4;  // float4 per batch
static constexpr int UNROLL = 8;

__global__ void __launch_bounds__(256) rev_cummax_kernel(
    const float4* __restrict__ in, float4* __restrict__ out)
{
    int col = blockIdx.x * blockDim.x + threadIdx.x;

    int b   = col >> 13;            // col / 8192
    int rem = col & (PER_B - 1);
    long top = (long)b * PER_B_ELEMS + rem + (long)(H - 1) * STRIDE_H;

    const float4* p = in  + top;
    float4*       q = out + top;

    float4 m = make_float4(-FLT_MAX, -FLT_MAX, -FLT_MAX, -FLT_MAX);

    #pragma unroll 1
    for (int it = 0; it < H / UNROLL; ++it) {
        float4 v[UNROLL];
        // Batch independent loads first — compiler emits 8 back-to-back
        // LDG.E.128 with no intervening dependency, maximizing MLP.
        #pragma unroll
        for (int j = 0; j < UNROLL; ++j)
            v[j] = __ldcs(p - (long)j * STRIDE_H);

        // Dependent suffix-max chain + streaming stores.
        #pragma unroll
        for (int j = 0; j < UNROLL; ++j) {
            m.x = fmaxf(m.x, v[j].x);
            m.y = fmaxf(m.y, v[j].y);
            m.z = fmaxf(m.z, v[j].z);
            m.w = fmaxf(m.w, v[j].w);
            __stcs(q - (long)j * STRIDE_H, m);
        }
        p -= (long)UNROLL * STRIDE_H;
        q -= (long)UNROLL * STRIDE_H;
    }
}

extern "C" void kernel_launch(void* const* d_in, const int* in_sizes, int n_in,
                              void* d_out, int out_size)
{
    (void)in_sizes; (void)n_in; (void)out_size;
    const float4* in  = (const float4*)d_in[0];
    float4*       out = (float4*)d_out;

    const int threads = 256;
    const int blocks  = COLS / threads;  // 512, exact
    rev_cummax_kernel<<<blocks, threads>>>(in, out);
}

// round 4
// speedup vs baseline: 1.0361x; 1.0361x over previous
#include <cuda_runtime.h>
#include <cfloat>

// Reverse cummax along axis 1 of [B=16, H=128, W=128, C=256] fp32.
// One thread per (b, w, c4) float4-column; walk h backward with running max.
// R3: 128-thread CTAs -> 1024 CTAs over 148 SMs (max/avg = 7/6.92), fixing the
// 4-vs-3 CTA per-SM imbalance that capped DRAM at ~74% with 512 CTAs.

static constexpr int B = 16;
static constexpr int H = 128;
static constexpr int W = 128;
static constexpr int C = 256;
static constexpr int C4 = C / 4;            // 64 float4 per row
static constexpr int STRIDE_H = W * C4;     // 8192 float4 between h slices
static constexpr int COLS = B * W * C4;     // 131072 columns
static constexpr int PER_B = W * C4;        // 8192 columns per batch
static constexpr long PER_B_ELEMS = (long)H * W * C4;

__global__ void __launch_bounds__(128) rev_cummax_kernel(
    const float4* __restrict__ in, float4* __restrict__ out)
{
    int col = blockIdx.x * blockDim.x + threadIdx.x;

    int b   = col >> 13;            // col / 8192
    int rem = col & (PER_B - 1);
    long base = (long)b * PER_B_ELEMS + rem;

    float4 m = make_float4(-FLT_MAX, -FLT_MAX, -FLT_MAX, -FLT_MAX);

    #pragma unroll 4
    for (int h = H - 1; h >= 0; --h) {
        long idx = base + (long)h * STRIDE_H;
        float4 v = in[idx];
        m.x = fmaxf(m.x, v.x);
        m.y = fmaxf(m.y, v.y);
        m.z = fmaxf(m.z, v.z);
        m.w = fmaxf(m.w, v.w);
        out[idx] = m;
    }
}

extern "C" void kernel_launch(void* const* d_in, const int* in_sizes, int n_in,
                              void* d_out, int out_size)
{
    (void)in_sizes; (void)n_in; (void)out_size;
    const float4* in  = (const float4*)d_in[0];
    float4*       out = (float4*)d_out;

    const int threads = 128;
    const int blocks  = COLS / threads;  // 1024, exact
    rev_cummax_kernel<<<blocks, threads>>>(in, out);
}